// round 6
// baseline (speedup 1.0000x reference)
#include <cuda_runtime.h>
#include <cstdint>

#define BB 16
#define SS 4096
#define FF 256
#define KK 512
#define PP 8
#define NITS 5
#define GRID 128
#define THREADS 512
#define NCHUNKS 8            // partial top-8 chunks per (b,k)
#define CHUNK_PTS 512        // points per chunk
#define FIXSCALE 1099511627776.0   // 2^40
#define NC 6                 // cells per axis
#define NCELLS 216
#define H2MARG 0.0276778f    // (1/6)^2 - 1e-4 safety margin

// ---------------- device scratch ----------------
static __device__ unsigned long long g_isum[3][BB * KK * 3];  // triple-buffered fixed-point sums
static __device__ int g_icnt[3][BB * KK];                     // triple-buffered counts
static __device__ unsigned long long g_part[(size_t)BB * KK * NCHUNKS * PP];
static __device__ unsigned g_bar_count = 0;
static __device__ unsigned g_bar_phase = 0;

// ---------------- FP helpers (semantics identical to the passing kernel) --------
__device__ __forceinline__ unsigned float_ord(float f) {
    unsigned u = __float_as_uint(f);
    return (u & 0x80000000u) ? ~u : (u | 0x80000000u);
}
__device__ __forceinline__ float ord_inv(unsigned u) {
    return __uint_as_float((u & 0x80000000u) ? (u & 0x7FFFFFFFu) : ~u);
}
__device__ __forceinline__ unsigned long long umin64(unsigned long long a, unsigned long long b) {
    return a < b ? a : b;
}
// mirrors jnp.sum(a*a,-1): elementwise mul then sequential reduce (no FMA contraction)
__device__ __forceinline__ float norm3_nofma(float a0, float a1, float a2) {
    return __fadd_rn(__fadd_rn(__fmul_rn(a0, a0), __fmul_rn(a1, a1)), __fmul_rn(a2, a2));
}
// ascending-d fma chain
__device__ __forceinline__ float dot3_fma(float a0, float a1, float a2,
                                          float b0, float b1, float b2) {
    return __fmaf_rn(a2, b2, __fmaf_rn(a1, b1, __fmul_rn(a0, b0)));
}
// (aa - 2*dot) + bb, reference grouping
__device__ __forceinline__ float sqdist_combine(float aa, float dot, float bb) {
    return __fadd_rn(__fmaf_rn(-2.0f, dot, aa), bb);
}
__device__ __forceinline__ int cellc(float x) {
    int i = (int)floorf(x * 6.0f);
    return i < 0 ? 0 : (i > 5 ? 5 : i);
}

__device__ __forceinline__ void sort8_bitonic(unsigned long long v[8]) {
#define CSWP(i, j) { unsigned long long lo = umin64(v[i], v[j]); \
                     unsigned long long hi = (v[i] < v[j]) ? v[j] : v[i]; \
                     v[i] = lo; v[j] = hi; }
    CSWP(0, 4) CSWP(1, 5) CSWP(2, 6) CSWP(3, 7)
    CSWP(0, 2) CSWP(1, 3) CSWP(4, 6) CSWP(5, 7)
    CSWP(0, 1) CSWP(2, 3) CSWP(4, 5) CSWP(6, 7)
#undef CSWP
}
__device__ __forceinline__ void merge8(unsigned long long a[8], const unsigned long long b[8]) {
    unsigned long long m[8];
#pragma unroll
    for (int i = 0; i < 8; i++) m[i] = umin64(a[i], b[7 - i]);
    sort8_bitonic(m);
#pragma unroll
    for (int i = 0; i < 8; i++) a[i] = m[i];
}

// ---------------- grid barrier (128 blocks < 148 SMs -> co-resident) ----
__device__ __forceinline__ void grid_sync() {
    __syncthreads();
    if (threadIdx.x == 0) {
        __threadfence();
        unsigned gen = atomicAdd(&g_bar_phase, 0u);
        if (atomicAdd(&g_bar_count, 1u) == GRID - 1) {
            g_bar_count = 0;
            __threadfence();
            atomicAdd(&g_bar_phase, 1u);  // release
        } else {
            while (atomicAdd(&g_bar_phase, 0u) == gen) __nanosleep(64);
        }
        __threadfence();
    }
    __syncthreads();
}

// ---------------- megakernel ----------------
__global__ void __launch_bounds__(THREADS, 1)
mega(const float* __restrict__ x, const float* __restrict__ pos, float* __restrict__ out) {
    __shared__ float4 s_sc[KK];           // 8KB: cell-sorted centroids (c0,c1,c2,|c|^2)
    __shared__ unsigned short s_sk[KK];   // 1KB: original k of sorted centroid
    __shared__ int s_cnt[256];            // 1KB: cell counters / scatter cursors
    __shared__ int s_scan[256];           // 1KB: scan buffer
    __shared__ int s_start[NCELLS + 1];   // cell slot starts (exclusive prefix)
    __shared__ float4 s4[1024];           // 16KB: staged points (topk)
    __shared__ int sidx[64][PP];          // 2KB: merged indices

    const int tid = threadIdx.x;
    const int blk = blockIdx.x;
    const int gtid = blk * THREADS + tid;
    const int b = blk >> 3;               // batch (8 blocks per batch)

    // ---- init: zero buffer 1 (W buffer of iteration 0) ----
    if (gtid < BB * KK) {
        g_icnt[1][gtid] = 0;
        g_isum[1][3 * gtid + 0] = 0ull;
        g_isum[1][3 * gtid + 1] = 0ull;
        g_isum[1][3 * gtid + 2] = 0ull;
    }
    grid_sync();

    // ---- k-means: 5 iterations, one barrier each ----
    // block handles 512 points: s = (blk&7)*512 + tid, one per thread
    const float* pp = pos + ((size_t)b * SS + (blk & 7) * 512 + tid) * 3;
    const float p0 = pp[0], p1 = pp[1], p2 = pp[2];
    const float pn = norm3_nofma(p0, p1, p2);
    const int pix = cellc(p0), piy = cellc(p1), piz = cellc(p2);
    const int pxlo = pix > 0 ? pix - 1 : 0, pxhi = pix < 5 ? pix + 1 : 5;
    const int pylo = piy > 0 ? piy - 1 : 0, pyhi = piy < 5 ? piy + 1 : 5;
    const int pzlo = piz > 0 ? piz - 1 : 0, pzhi = piz < 5 ? piz + 1 : 5;

    const unsigned long long addA =
        (unsigned long long)__double2ll_rn((double)p0 * FIXSCALE);
    const unsigned long long addB =
        (unsigned long long)__double2ll_rn((double)p1 * FIXSCALE);
    const unsigned long long addC =
        (unsigned long long)__double2ll_rn((double)p2 * FIXSCALE);

    for (int it = 0; it < NITS; it++) {
        const int Rb = it % 3;
        const int Wb = (it + 1) % 3;
        const int Zb = (it + 2) % 3;

        // ---- compute this batch's centroid k = tid (exactly 512 threads) ----
        float c0, c1, c2;
        if (it == 0) {
            const float* cp = pos + ((size_t)b * SS + tid) * 3;
            c0 = cp[0]; c1 = cp[1]; c2 = cp[2];
        } else {
            int slot = b * KK + tid;
            float cnt = (float)g_icnt[Rb][slot];
            cnt = cnt > 1.0f ? cnt : 1.0f;
            c0 = __fdiv_rn((float)((double)(long long)g_isum[Rb][3 * slot + 0] * (1.0 / FIXSCALE)), cnt);
            c1 = __fdiv_rn((float)((double)(long long)g_isum[Rb][3 * slot + 1] * (1.0 / FIXSCALE)), cnt);
            c2 = __fdiv_rn((float)((double)(long long)g_isum[Rb][3 * slot + 2] * (1.0 / FIXSCALE)), cnt);
        }
        const float cn = norm3_nofma(c0, c1, c2);
        // cell id = (z*6 + y)*6 + x  (x innermost)
        const int mycell = (cellc(c2) * NC + cellc(c1)) * NC + cellc(c0);

        // ---- bin centroids: count -> scan -> scatter ----
        if (tid < 256) s_cnt[tid] = 0;
        // zero this block's slice of the Z buffer (independent work)
        if (tid < 64) {
            int slot = blk * 64 + tid;
            g_icnt[Zb][slot] = 0;
            g_isum[Zb][3 * slot + 0] = 0ull;
            g_isum[Zb][3 * slot + 1] = 0ull;
            g_isum[Zb][3 * slot + 2] = 0ull;
        }
        __syncthreads();
        atomicAdd(&s_cnt[mycell], 1);
        __syncthreads();
        if (tid < 256) s_scan[tid] = s_cnt[tid];
        __syncthreads();
#pragma unroll
        for (int off = 1; off < 256; off <<= 1) {
            int v2 = 0;
            if (tid < 256) { v2 = s_scan[tid]; if (tid >= off) v2 += s_scan[tid - off]; }
            __syncthreads();
            if (tid < 256) s_scan[tid] = v2;
            __syncthreads();
        }
        if (tid == 0) s_start[0] = 0;
        if (tid < NCELLS) {
            s_start[tid + 1] = s_scan[tid];
            s_cnt[tid] = (tid == 0) ? 0 : s_scan[tid - 1];   // scatter cursors
        }
        __syncthreads();
        {
            int slot = atomicAdd(&s_cnt[mycell], 1);
            s_sc[slot] = make_float4(c0, c1, c2, cn);
            s_sk[slot] = (unsigned short)tid;
        }
        __syncthreads();

        // ---- assign via 27-cell exact pruning ----
        unsigned long long bkey = 0xFFFFFFFFFFFFFFFFull;
        for (int z = pzlo; z <= pzhi; z++) {
            for (int y = pylo; y <= pyhi; y++) {
                int row = (z * NC + y) * NC;
                int t0 = s_start[row + pxlo];
                int t1 = s_start[row + pxhi + 1];
                for (int t = t0; t < t1; t++) {
                    float4 c = s_sc[t];
                    float dot = dot3_fma(p0, p1, p2, c.x, c.y, c.z);
                    float v = sqdist_combine(pn, dot, c.w);
                    unsigned long long key =
                        ((unsigned long long)float_ord(v) << 32) | s_sk[t];
                    bkey = umin64(bkey, key);
                }
            }
        }
        {
            float bestv = ord_inv((unsigned)(bkey >> 32));
            bool need = !(bestv < H2MARG);   // also true if no candidate (NaN)
            if (__any_sync(0xFFFFFFFFu, need)) {   // rare: P ~ 5e-5/point
                for (int t = 0; t < KK; t++) {
                    float4 c = s_sc[t];
                    float dot = dot3_fma(p0, p1, p2, c.x, c.y, c.z);
                    float v = sqdist_combine(pn, dot, c.w);
                    unsigned long long key =
                        ((unsigned long long)float_ord(v) << 32) | s_sk[t];
                    if (need) bkey = umin64(bkey, key);
                }
            }
        }
        const int bi = (int)(bkey & 0xFFFFull);
        {
            unsigned long long* sm = &g_isum[Wb][((size_t)b * KK + bi) * 3];
            atomicAdd(sm + 0, addA);
            atomicAdd(sm + 1, addB);
            atomicAdd(sm + 2, addC);
            atomicAdd(&g_icnt[Wb][b * KK + bi], 1);
        }
        grid_sync();
    }

    // ---- top-8: final centroids live in buffer (NITS % 3) == 2 ----
    {
        const int FB = NITS % 3;
        const int unit = blk & 7;
        const int kc = unit >> 2;             // 0..1: which 256 centroids
        const int sc_ = unit & 3;             // 0..3: which 1024-point chunk
        const int shalf = tid >> 8;           // 0..1: which 512-point half
        const int k = kc * 256 + (tid & 255);
        const int chunk = sc_ * 2 + shalf;    // 0..7
        const int sbase = sc_ * 1024 + shalf * CHUNK_PTS;

        const int slot = b * KK + k;
        float cnt = (float)g_icnt[FB][slot];
        cnt = cnt > 1.0f ? cnt : 1.0f;
        float c0 = __fdiv_rn((float)((double)(long long)g_isum[FB][3 * slot + 0] * (1.0 / FIXSCALE)), cnt);
        float c1 = __fdiv_rn((float)((double)(long long)g_isum[FB][3 * slot + 1] * (1.0 / FIXSCALE)), cnt);
        float c2 = __fdiv_rn((float)((double)(long long)g_isum[FB][3 * slot + 2] * (1.0 / FIXSCALE)), cnt);
        float cn = norm3_nofma(c0, c1, c2);

        // stage the block's 1024-point chunk
        for (int i = tid; i < 1024; i += THREADS) {
            const float* qp = pos + ((size_t)b * SS + sc_ * 1024 + i) * 3;
            float q0 = qp[0], q1 = qp[1], q2 = qp[2];
            s4[i] = make_float4(q0, q1, q2, norm3_nofma(q0, q1, q2));
        }
        __syncthreads();

        unsigned long long l[8];
#pragma unroll
        for (int j = 0; j < 8; j++) l[j] = 0xFF800000FFFFFFFFull;   // ord(+inf) | idx_max
        float thresh = __int_as_float(0x7f800000);

        const int ibase = shalf * CHUNK_PTS;
#pragma unroll 4
        for (int i = 0; i < CHUNK_PTS; i++) {
            float4 p = s4[ibase + i];
            float dot = dot3_fma(c0, c1, c2, p.x, p.y, p.z);
            float v = sqdist_combine(cn, dot, p.w);
            if (v < thresh) {
                float vc = (v == 0.0f) ? 0.0f : v;   // canonicalize -0.0
                unsigned long long key =
                    ((unsigned long long)float_ord(vc) << 32) | (unsigned)(sbase + i);
                l[7] = key;
#pragma unroll
                for (int j = 7; j > 0; --j) {
                    if (l[j] < l[j - 1]) {
                        unsigned long long t = l[j]; l[j] = l[j - 1]; l[j - 1] = t;
                    }
                }
                thresh = ord_inv((unsigned)(l[7] >> 32));
            }
        }
        unsigned long long* outp = g_part + ((size_t)slot * NCHUNKS + chunk) * PP;
#pragma unroll
        for (int j = 0; j < 8; j++) outp[j] = l[j];
    }
    grid_sync();

    // ---- merge + gather-mean: 64 (b,k) units per block ----
    if (tid < 64) {
        int bk = blk * 64 + tid;
        const unsigned long long* gp = g_part + (size_t)bk * NCHUNKS * PP;
        unsigned long long a[8], t[8];
#pragma unroll
        for (int j = 0; j < 8; j++) a[j] = gp[j];
#pragma unroll
        for (int c = 1; c < NCHUNKS; c++) {
#pragma unroll
            for (int j = 0; j < 8; j++) t[j] = gp[c * 8 + j];
            merge8(a, t);
        }
#pragma unroll
        for (int j = 0; j < 8; j++) sidx[tid][j] = (int)(unsigned)a[j];
    }
    __syncthreads();

    // gather: f = tid&255, two units in flight (tid>>8)
    {
        const float* xb = x + (size_t)b * SS * FF;
        const int f = tid & 255;
        const int uoff = tid >> 8;
        for (int uu = 0; uu < 32; uu++) {
            int u = uu * 2 + uoff;
            float acc = 0.0f;
#pragma unroll
            for (int p = 0; p < 8; p++)
                acc += __ldg(&xb[(size_t)sidx[u][p] * FF + f]);
            out[(size_t)(blk * 64 + u) * FF + f] = acc * 0.125f;
        }
    }
}

// ---------------- launch ----------------
extern "C" void kernel_launch(void* const* d_in, const int* in_sizes, int n_in,
                              void* d_out, int out_size) {
    const float* x   = (const float*)d_in[0];   // (B,S,F) f32
    const float* pos = (const float*)d_in[1];   // (B,S,D) f32
    float* out = (float*)d_out;                 // (B,K,F) f32
    (void)in_sizes; (void)n_in; (void)out_size;

    mega<<<GRID, THREADS>>>(x, pos, out);
}

// round 7
// speedup vs baseline: 1.2338x; 1.2338x over previous
#include <cuda_runtime.h>
#include <cstdint>

#define BB 16
#define SS 4096
#define FF 256
#define KK 512
#define PP 8
#define NITS 5
#define GRID 128
#define THREADS 512
#define FIXSCALE 1099511627776.0   // 2^40
#define NC 6
#define NCELLS 216
#define H2MARG 0.0276778f          // (1/6)^2 - 1e-4 safety margin

typedef unsigned long long u64;
typedef unsigned short u16;

// ---------------- device scratch ----------------
static __device__ u64 g_isum[3][BB * KK * 3];   // triple-buffered fixed-point sums
static __device__ int g_icnt[3][BB * KK];       // triple-buffered counts
static __device__ unsigned g_bar_count = 0;
static __device__ unsigned g_bar_phase = 0;

// ---------------- dynamic smem union ----------------
struct SA {                       // assign phase (~21KB)
    float4 sc[KK];                // cell-sorted centroids (c0,c1,c2,|c|^2)
    u16 sk[KK];                   // original k of sorted centroid
    int cnt[256];
    int scan[256];
    int start[256];
    float4 sp[KK];                // cell-sorted points (transient, load->regs)
};
struct ST {                       // topk phase (~112KB)
    float4 tp[SS];                // cell-sorted points of the batch
    u16 tpi[SS];                  // original s of sorted point
    u64 part[64][8][PP];          // per-centroid 8 partial top-8 lists
    int cnt[256];
    int scan[256];
    int start[256];
    int sidx[64][PP];
    int fblist[64];
    int fbn;
};
union SU { SA a; ST t; };

// ---------------- FP helpers (reference-exact semantics) --------
__device__ __forceinline__ unsigned float_ord(float f) {
    unsigned u = __float_as_uint(f);
    return (u & 0x80000000u) ? ~u : (u | 0x80000000u);
}
__device__ __forceinline__ float ord_inv(unsigned u) {
    return __uint_as_float((u & 0x80000000u) ? (u & 0x7FFFFFFFu) : ~u);
}
__device__ __forceinline__ u64 umin64(u64 a, u64 b) { return a < b ? a : b; }
// mirrors jnp.sum(a*a,-1): elementwise mul then sequential reduce (no FMA contraction)
__device__ __forceinline__ float norm3_nofma(float a0, float a1, float a2) {
    return __fadd_rn(__fadd_rn(__fmul_rn(a0, a0), __fmul_rn(a1, a1)), __fmul_rn(a2, a2));
}
// ascending-d fma chain
__device__ __forceinline__ float dot3_fma(float a0, float a1, float a2,
                                          float b0, float b1, float b2) {
    return __fmaf_rn(a2, b2, __fmaf_rn(a1, b1, __fmul_rn(a0, b0)));
}
// (aa - 2*dot) + bb, reference grouping
__device__ __forceinline__ float sqdist_combine(float aa, float dot, float bb) {
    return __fadd_rn(__fmaf_rn(-2.0f, dot, aa), bb);
}
__device__ __forceinline__ int cellc(float x) {
    int i = (int)floorf(x * 6.0f);
    return i < 0 ? 0 : (i > 5 ? 5 : i);
}

__device__ __forceinline__ void sort8_bitonic(u64 v[8]) {
#define CSWP(i, j) { u64 lo = umin64(v[i], v[j]); \
                     u64 hi = (v[i] < v[j]) ? v[j] : v[i]; \
                     v[i] = lo; v[j] = hi; }
    CSWP(0, 4) CSWP(1, 5) CSWP(2, 6) CSWP(3, 7)
    CSWP(0, 2) CSWP(1, 3) CSWP(4, 6) CSWP(5, 7)
    CSWP(0, 1) CSWP(2, 3) CSWP(4, 5) CSWP(6, 7)
#undef CSWP
}
__device__ __forceinline__ void merge8(u64 a[8], const u64 b[8]) {
    u64 m[8];
#pragma unroll
    for (int i = 0; i < 8; i++) m[i] = umin64(a[i], b[7 - i]);
    sort8_bitonic(m);
#pragma unroll
    for (int i = 0; i < 8; i++) a[i] = m[i];
}

// sorted-insert into top-8 list; <= lets equal-dist smaller-idx keys reach the key compare
__device__ __forceinline__ void top8_insert(u64 l[PP], float& thresh, float v, unsigned idx) {
    if (v <= thresh) {
        float vc = (v == 0.0f) ? 0.0f : v;   // canonicalize -0.0
        u64 key = ((u64)float_ord(vc) << 32) | idx;
        if (key < l[7]) {
            l[7] = key;
#pragma unroll
            for (int j = 7; j > 0; --j)
                if (l[j] < l[j - 1]) { u64 tt = l[j]; l[j] = l[j - 1]; l[j - 1] = tt; }
            thresh = ord_inv((unsigned)(l[7] >> 32));
        }
    }
}

// counts in cnt[] -> exclusive starts in start[0..NCELLS], scatter cursors back in cnt[]
__device__ __forceinline__ void bin_scan(int* cnt, int* scan, int* start, int tid) {
    if (tid < 256) scan[tid] = cnt[tid];
    __syncthreads();
#pragma unroll
    for (int off = 1; off < 256; off <<= 1) {
        int v = 0;
        if (tid < 256) { v = scan[tid]; if (tid >= off) v += scan[tid - off]; }
        __syncthreads();
        if (tid < 256) scan[tid] = v;
        __syncthreads();
    }
    if (tid == 0) start[0] = 0;
    if (tid < NCELLS) {
        start[tid + 1] = scan[tid];
        cnt[tid] = (tid == 0) ? 0 : scan[tid - 1];
    }
    __syncthreads();
}

// ---------------- grid barrier (128 blocks < 148 SMs -> co-resident) ----
__device__ __forceinline__ void grid_sync() {
    __syncthreads();
    if (threadIdx.x == 0) {
        __threadfence();
        unsigned gen = atomicAdd(&g_bar_phase, 0u);
        if (atomicAdd(&g_bar_count, 1u) == GRID - 1) {
            g_bar_count = 0;
            __threadfence();
            atomicAdd(&g_bar_phase, 1u);  // release
        } else {
            while (atomicAdd(&g_bar_phase, 0u) == gen) __nanosleep(64);
        }
        __threadfence();
    }
    __syncthreads();
}

// reconstruct centroid k of batch b from accumulator buffer fb
__device__ __forceinline__ void load_centroid(int fb, int b, int k,
                                              float& c0, float& c1, float& c2) {
    int slot = b * KK + k;
    float cnt = (float)g_icnt[fb][slot];
    cnt = cnt > 1.0f ? cnt : 1.0f;
    c0 = __fdiv_rn((float)((double)(long long)g_isum[fb][3 * slot + 0] * (1.0 / FIXSCALE)), cnt);
    c1 = __fdiv_rn((float)((double)(long long)g_isum[fb][3 * slot + 1] * (1.0 / FIXSCALE)), cnt);
    c2 = __fdiv_rn((float)((double)(long long)g_isum[fb][3 * slot + 2] * (1.0 / FIXSCALE)), cnt);
}

// ---------------- megakernel ----------------
__global__ void __launch_bounds__(THREADS, 1)
mega(const float* __restrict__ x, const float* __restrict__ pos, float* __restrict__ out) {
    extern __shared__ char smem_raw[];
    SU* su = reinterpret_cast<SU*>(smem_raw);

    const int tid = threadIdx.x;
    const int blk = blockIdx.x;
    const int gtid = blk * THREADS + tid;
    const int b = blk >> 3;               // batch (8 blocks per batch)
    const int grp = blk & 7;              // group within batch

    // ---- init: zero buffer 1 (W buffer of iteration 0) ----
    if (gtid < BB * KK) {
        g_icnt[1][gtid] = 0;
        g_isum[1][3 * gtid + 0] = 0ull;
        g_isum[1][3 * gtid + 1] = 0ull;
        g_isum[1][3 * gtid + 2] = 0ull;
    }

    // ================= ASSIGN PHASE =================
    SA& sa = su->a;

    // ---- sort this block's 512 points by cell (once) ----
    float p0, p1, p2, pn;
    {
        const float* pp = pos + ((size_t)b * SS + grp * 512 + tid) * 3;
        float q0 = pp[0], q1 = pp[1], q2 = pp[2];
        int mycell = (cellc(q2) * NC + cellc(q1)) * NC + cellc(q0);
        if (tid < 256) sa.cnt[tid] = 0;
        __syncthreads();
        atomicAdd(&sa.cnt[mycell], 1);
        __syncthreads();
        bin_scan(sa.cnt, sa.scan, sa.start, tid);
        int slot = atomicAdd(&sa.cnt[mycell], 1);
        sa.sp[slot] = make_float4(q0, q1, q2, norm3_nofma(q0, q1, q2));
        __syncthreads();
        float4 mine = sa.sp[tid];
        p0 = mine.x; p1 = mine.y; p2 = mine.z; pn = mine.w;
    }
    const int pix = cellc(p0), piy = cellc(p1), piz = cellc(p2);
    const int pxlo = pix > 0 ? pix - 1 : 0, pxhi = pix < 5 ? pix + 1 : 5;
    const int pylo = piy > 0 ? piy - 1 : 0, pyhi = piy < 5 ? piy + 1 : 5;
    const int pzlo = piz > 0 ? piz - 1 : 0, pzhi = piz < 5 ? piz + 1 : 5;
    const u64 addA = (u64)__double2ll_rn((double)p0 * FIXSCALE);
    const u64 addB = (u64)__double2ll_rn((double)p1 * FIXSCALE);
    const u64 addC = (u64)__double2ll_rn((double)p2 * FIXSCALE);

    grid_sync();   // covers init-zero AND point sort

    for (int it = 0; it < NITS; it++) {
        const int Rb = it % 3;
        const int Wb = (it + 1) % 3;
        const int Zb = (it + 2) % 3;

        // centroid k = tid
        float c0, c1, c2;
        if (it == 0) {
            const float* cp = pos + ((size_t)b * SS + tid) * 3;
            c0 = cp[0]; c1 = cp[1]; c2 = cp[2];
        } else {
            load_centroid(Rb, b, tid, c0, c1, c2);
        }
        const float cn = norm3_nofma(c0, c1, c2);
        const int ccell = (cellc(c2) * NC + cellc(c1)) * NC + cellc(c0);

        if (tid < 256) sa.cnt[tid] = 0;
        if (tid < 64) {           // zero Z-buffer slice (independent)
            int slot = blk * 64 + tid;
            g_icnt[Zb][slot] = 0;
            g_isum[Zb][3 * slot + 0] = 0ull;
            g_isum[Zb][3 * slot + 1] = 0ull;
            g_isum[Zb][3 * slot + 2] = 0ull;
        }
        __syncthreads();
        atomicAdd(&sa.cnt[ccell], 1);
        __syncthreads();
        bin_scan(sa.cnt, sa.scan, sa.start, tid);
        {
            int slot = atomicAdd(&sa.cnt[ccell], 1);
            sa.sc[slot] = make_float4(c0, c1, c2, cn);
            sa.sk[slot] = (u16)tid;
        }
        __syncthreads();

        // pruned argmin: warp-coherent 27-cell scan
        u64 bkey = 0xFFFFFFFFFFFFFFFFull;
        for (int z = pzlo; z <= pzhi; z++) {
            for (int y = pylo; y <= pyhi; y++) {
                int row = (z * NC + y) * NC;
                int t0 = sa.start[row + pxlo];
                int t1 = sa.start[row + pxhi + 1];
                for (int t = t0; t < t1; t++) {
                    float4 c = sa.sc[t];
                    float dot = dot3_fma(p0, p1, p2, c.x, c.y, c.z);
                    float v = sqdist_combine(pn, dot, c.w);
                    u64 key = ((u64)float_ord(v) << 32) | sa.sk[t];
                    bkey = umin64(bkey, key);
                }
            }
        }
        {
            float bestv = ord_inv((unsigned)(bkey >> 32));
            bool need = !(bestv < H2MARG);        // also catches empty (NaN)
            if (__any_sync(0xFFFFFFFFu, need)) {  // rare
                for (int t = 0; t < KK; t++) {
                    float4 c = sa.sc[t];
                    float dot = dot3_fma(p0, p1, p2, c.x, c.y, c.z);
                    float v = sqdist_combine(pn, dot, c.w);
                    u64 key = ((u64)float_ord(v) << 32) | sa.sk[t];
                    if (need) bkey = umin64(bkey, key);
                }
            }
        }
        const int bi = (int)(bkey & 0xFFFFull);
        {
            u64* sm = &g_isum[Wb][((size_t)b * KK + bi) * 3];
            atomicAdd(sm + 0, addA);
            atomicAdd(sm + 1, addB);
            atomicAdd(sm + 2, addC);
            atomicAdd(&g_icnt[Wb][b * KK + bi], 1);
        }
        grid_sync();
    }

    // ================= TOPK PHASE (all in-block from here) =================
    ST& st = su->t;
    const int FB = NITS % 3;   // final accumulator buffer = 2

    // ---- bin all 4096 batch points by cell ----
    if (tid < 256) st.cnt[tid] = 0;
    if (tid == 0) st.fbn = 0;
    __syncthreads();
#pragma unroll
    for (int j = 0; j < 8; j++) {
        int i = j * 512 + tid;
        const float* qp = pos + ((size_t)b * SS + i) * 3;
        int cell = (cellc(qp[2]) * NC + cellc(qp[1])) * NC + cellc(qp[0]);
        atomicAdd(&st.cnt[cell], 1);
    }
    __syncthreads();
    bin_scan(st.cnt, st.scan, st.start, tid);
#pragma unroll
    for (int j = 0; j < 8; j++) {
        int i = j * 512 + tid;
        const float* qp = pos + ((size_t)b * SS + i) * 3;
        float q0 = qp[0], q1 = qp[1], q2 = qp[2];
        int cell = (cellc(q2) * NC + cellc(q1)) * NC + cellc(q0);
        int slot = atomicAdd(&st.cnt[cell], 1);
        st.tp[slot] = make_float4(q0, q1, q2, norm3_nofma(q0, q1, q2));
        st.tpi[slot] = (u16)i;
    }
    __syncthreads();

    // ---- pruned top-8: 8 threads per centroid, stride-8 over 27-cell neighborhood ----
    {
        const int u = tid >> 3;           // local centroid 0..63
        const int j = tid & 7;            // lane within group
        const int k = grp * 64 + u;
        float c0, c1, c2;
        load_centroid(FB, b, k, c0, c1, c2);
        const float cn = norm3_nofma(c0, c1, c2);
        const int cx = cellc(c0), cy = cellc(c1), cz = cellc(c2);
        const int xlo = cx > 0 ? cx - 1 : 0, xhi = cx < 5 ? cx + 1 : 5;
        const int ylo = cy > 0 ? cy - 1 : 0, yhi = cy < 5 ? cy + 1 : 5;
        const int zlo = cz > 0 ? cz - 1 : 0, zhi = cz < 5 ? cz + 1 : 5;

        u64 l[PP];
#pragma unroll
        for (int q = 0; q < PP; q++) l[q] = 0xFF800000FFFFFFFFull;  // ord(+inf)|idx_max
        float thresh = __int_as_float(0x7f800000);

        for (int z = zlo; z <= zhi; z++) {
            for (int y = ylo; y <= yhi; y++) {
                int row = (z * NC + y) * NC;
                int t0 = st.start[row + xlo];
                int t1 = st.start[row + xhi + 1];
                for (int t = t0 + j; t < t1; t += 8) {
                    float4 p = st.tp[t];
                    float dot = dot3_fma(c0, c1, c2, p.x, p.y, p.z);
                    float v = sqdist_combine(cn, dot, p.w);
                    top8_insert(l, thresh, v, (unsigned)st.tpi[t]);
                }
            }
        }
#pragma unroll
        for (int q = 0; q < PP; q++) st.part[u][j][q] = l[q];
    }
    __syncthreads();

    // ---- merge 8 partials per centroid; flag fallbacks ----
    if (tid < 64) {
        u64 a[PP];
#pragma unroll
        for (int q = 0; q < PP; q++) a[q] = st.part[tid][0][q];
#pragma unroll
        for (int c = 1; c < 8; c++) merge8(a, st.part[tid][c]);
#pragma unroll
        for (int q = 0; q < PP; q++) st.sidx[tid][q] = (int)(a[q] & 0xFFFFu);
        float d7 = ord_inv((unsigned)(a[7] >> 32));
        if (!(d7 < H2MARG)) {
            int i = atomicAdd(&st.fbn, 1);
            st.fblist[i] = tid;
        }
    }
    __syncthreads();

    // ---- cooperative fallback: one warp per flagged centroid, exact full scan ----
    {
        const int warp = tid >> 5, lane = tid & 31;
        const int nfb = st.fbn;
        for (int i = warp; i < nfb; i += 16) {
            int u = st.fblist[i];
            int k = grp * 64 + u;
            float c0, c1, c2;
            load_centroid(FB, b, k, c0, c1, c2);
            float cn = norm3_nofma(c0, c1, c2);
            u64 l[PP];
#pragma unroll
            for (int q = 0; q < PP; q++) l[q] = 0xFF800000FFFFFFFFull;
            float thresh = __int_as_float(0x7f800000);
            for (int t = lane; t < SS; t += 32) {
                float4 p = st.tp[t];
                float dot = dot3_fma(c0, c1, c2, p.x, p.y, p.z);
                float v = sqdist_combine(cn, dot, p.w);
                top8_insert(l, thresh, v, (unsigned)st.tpi[t]);
            }
            // 32 lane-lists -> warp's scratch region (its own 4 centroids' dead slots)
            u64* reg = &st.part[4 * warp][0][0];   // 256 slots
#pragma unroll
            for (int q = 0; q < PP; q++) reg[lane * 8 + q] = l[q];
            __syncwarp();
            if (lane == 0) {
                u64 a[PP];
#pragma unroll
                for (int q = 0; q < PP; q++) a[q] = reg[q];
                for (int c = 1; c < 32; c++) merge8(a, &reg[c * 8]);
#pragma unroll
                for (int q = 0; q < PP; q++) st.sidx[u][q] = (int)(a[q] & 0xFFFFu);
            }
            __syncwarp();
        }
    }
    __syncthreads();

    // ---- gather-mean: block's 64 centroids, f = tid&255 ----
    {
        const float* xb = x + (size_t)b * SS * FF;
        const int f = tid & 255;
        const int uoff = tid >> 8;
        const size_t obase = ((size_t)b * KK + grp * 64) * FF;
        for (int uu = 0; uu < 32; uu++) {
            int u = uu * 2 + uoff;
            float acc = 0.0f;
#pragma unroll
            for (int p = 0; p < 8; p++)
                acc += __ldg(&xb[(size_t)st.sidx[u][p] * FF + f]);
            out[obase + (size_t)u * FF + f] = acc * 0.125f;
        }
    }
}

// ---------------- launch ----------------
extern "C" void kernel_launch(void* const* d_in, const int* in_sizes, int n_in,
                              void* d_out, int out_size) {
    const float* x   = (const float*)d_in[0];   // (B,S,F) f32
    const float* pos = (const float*)d_in[1];   // (B,S,D) f32
    float* out = (float*)d_out;                 // (B,K,F) f32
    (void)in_sizes; (void)n_in; (void)out_size;

    cudaFuncSetAttribute(mega, cudaFuncAttributeMaxDynamicSharedMemorySize,
                         (int)sizeof(SU));
    mega<<<GRID, THREADS, sizeof(SU)>>>(x, pos, out);
}

// round 8
// speedup vs baseline: 1.8616x; 1.5088x over previous
#include <cuda_runtime.h>
#include <cstdint>

#define BB 16
#define SS 4096
#define FF 256
#define KK 512
#define PP 8
#define NITS 5
#define GRID 128
#define THREADS 512
#define FIXSCALE 1099511627776.0   // 2^40
#define NC 6
#define NCELLS 216
#define H2MARG 0.0276778f          // (1/6)^2 - 1e-4 safety margin

typedef unsigned long long u64;
typedef unsigned short u16;

// ---------------- device scratch ----------------
static __device__ u64 g_isum[3][BB * KK * 3];   // triple-buffered fixed-point sums
static __device__ int g_icnt[3][BB * KK];       // triple-buffered counts
static __device__ unsigned g_bar_count = 0;
static __device__ unsigned g_bar_phase = 0;

// ---------------- dynamic smem layout ----------------
struct SP {
    float4 tp[SS];        // 64KB: batch points, cell-sorted (persistent)
    u16 tpi[SS];          // 8KB: original s of sorted point (persistent)
    int startP[257];      // point-cell starts (persistent)
    int wsums[8];         // scan scratch
    int cut[9];           // cell-aligned block slice cuts
    union {
        struct {          // assign phase (~11KB)
            float4 sc[KK];      // cell-sorted centroids
            u16 sk[KK];         // original k
            int cntC[256];      // counters / cursors (also used for point binning)
            int startC[257];
        } a;
        struct {          // topk phase (~35KB)
            u64 part[64][8][PP];
            int sidx[64][PP];
            int fblist[64];
            int fbn;            // beyond sizeof(a): no overlap hazard
        } t;
    } u;
};

// ---------------- FP helpers (reference-exact semantics) --------
__device__ __forceinline__ unsigned float_ord(float f) {
    unsigned u = __float_as_uint(f);
    return (u & 0x80000000u) ? ~u : (u | 0x80000000u);
}
__device__ __forceinline__ float ord_inv(unsigned u) {
    return __uint_as_float((u & 0x80000000u) ? (u & 0x7FFFFFFFu) : ~u);
}
__device__ __forceinline__ u64 umin64(u64 a, u64 b) { return a < b ? a : b; }
// mirrors jnp.sum(a*a,-1): elementwise mul then sequential reduce (no FMA contraction)
__device__ __forceinline__ float norm3_nofma(float a0, float a1, float a2) {
    return __fadd_rn(__fadd_rn(__fmul_rn(a0, a0), __fmul_rn(a1, a1)), __fmul_rn(a2, a2));
}
// ascending-d fma chain
__device__ __forceinline__ float dot3_fma(float a0, float a1, float a2,
                                          float b0, float b1, float b2) {
    return __fmaf_rn(a2, b2, __fmaf_rn(a1, b1, __fmul_rn(a0, b0)));
}
// (aa - 2*dot) + bb, reference grouping
__device__ __forceinline__ float sqdist_combine(float aa, float dot, float bb) {
    return __fadd_rn(__fmaf_rn(-2.0f, dot, aa), bb);
}
__device__ __forceinline__ int cellc(float x) {
    int i = (int)floorf(x * 6.0f);
    return i < 0 ? 0 : (i > 5 ? 5 : i);
}

__device__ __forceinline__ void sort8_bitonic(u64 v[8]) {
#define CSWP(i, j) { u64 lo = umin64(v[i], v[j]); \
                     u64 hi = (v[i] < v[j]) ? v[j] : v[i]; \
                     v[i] = lo; v[j] = hi; }
    CSWP(0, 4) CSWP(1, 5) CSWP(2, 6) CSWP(3, 7)
    CSWP(0, 2) CSWP(1, 3) CSWP(4, 6) CSWP(5, 7)
    CSWP(0, 1) CSWP(2, 3) CSWP(4, 5) CSWP(6, 7)
#undef CSWP
}
__device__ __forceinline__ void merge8(u64 a[8], const u64 b[8]) {
    u64 m[8];
#pragma unroll
    for (int i = 0; i < 8; i++) m[i] = umin64(a[i], b[7 - i]);
    sort8_bitonic(m);
#pragma unroll
    for (int i = 0; i < 8; i++) a[i] = m[i];
}

// sorted-insert; <= lets equal-dist smaller-idx keys reach the key compare
__device__ __forceinline__ void top8_insert(u64 l[PP], float& thresh, float v, unsigned idx) {
    if (v <= thresh) {
        float vc = (v == 0.0f) ? 0.0f : v;   // canonicalize -0.0
        u64 key = ((u64)float_ord(vc) << 32) | idx;
        if (key < l[7]) {
            l[7] = key;
#pragma unroll
            for (int j = 7; j > 0; --j)
                if (l[j] < l[j - 1]) { u64 tt = l[j]; l[j] = l[j - 1]; l[j - 1] = tt; }
            thresh = ord_inv((unsigned)(l[7] >> 32));
        }
    }
}

// shfl-based 256-entry scan: counts in cnt[] -> starts in startArr[0..256],
// exclusive cursors written back into cnt[]. 3 block barriers.
__device__ __forceinline__ void scan256(int* cnt, int* startArr, int* wsums, int tid) {
    int w = tid >> 5, lane = tid & 31;
    int orig = 0, v = 0;
    if (tid < 256) {
        orig = cnt[tid]; v = orig;
#pragma unroll
        for (int off = 1; off < 32; off <<= 1) {
            int n = __shfl_up_sync(0xFFFFFFFFu, v, off);
            if (lane >= off) v += n;
        }
        if (lane == 31) wsums[w] = v;
    }
    __syncthreads();
    if (tid < 8) {
        int s = wsums[tid];
#pragma unroll
        for (int off = 1; off < 8; off <<= 1) {
            int n = __shfl_up_sync(0xFFu, s, off);
            if (tid >= off) s += n;
        }
        wsums[tid] = s;
    }
    __syncthreads();
    if (tid < 256) {
        int incl = v + (w > 0 ? wsums[w - 1] : 0);
        startArr[tid + 1] = incl;
        cnt[tid] = incl - orig;       // exclusive prefix = scatter cursor
    }
    if (tid == 0) startArr[0] = 0;
    __syncthreads();
}

// ---------------- grid barrier (128 blocks < 148 SMs -> co-resident) ----
__device__ __forceinline__ void grid_sync() {
    __syncthreads();
    if (threadIdx.x == 0) {
        __threadfence();
        unsigned gen = atomicAdd(&g_bar_phase, 0u);
        if (atomicAdd(&g_bar_count, 1u) == GRID - 1) {
            g_bar_count = 0;
            __threadfence();
            atomicAdd(&g_bar_phase, 1u);  // release
        } else {
            while (atomicAdd(&g_bar_phase, 0u) == gen) __nanosleep(64);
        }
        __threadfence();
    }
    __syncthreads();
}

__device__ __forceinline__ void load_centroid(int fb, int b, int k,
                                              float& c0, float& c1, float& c2) {
    int slot = b * KK + k;
    float cnt = (float)g_icnt[fb][slot];
    cnt = cnt > 1.0f ? cnt : 1.0f;
    c0 = __fdiv_rn((float)((double)(long long)g_isum[fb][3 * slot + 0] * (1.0 / FIXSCALE)), cnt);
    c1 = __fdiv_rn((float)((double)(long long)g_isum[fb][3 * slot + 1] * (1.0 / FIXSCALE)), cnt);
    c2 = __fdiv_rn((float)((double)(long long)g_isum[fb][3 * slot + 2] * (1.0 / FIXSCALE)), cnt);
}

// ---------------- megakernel ----------------
__global__ void __launch_bounds__(THREADS, 1)
mega(const float* __restrict__ x, const float* __restrict__ pos, float* __restrict__ out) {
    extern __shared__ char smem_raw[];
    SP* sp = reinterpret_cast<SP*>(smem_raw);

    const int tid = threadIdx.x;
    const int blk = blockIdx.x;
    const int gtid = blk * THREADS + tid;
    const int b = blk >> 3;               // batch (8 blocks per batch)
    const int grp = blk & 7;              // group within batch

    // ---- init: zero buffer 1 (W buffer of iteration 0) ----
    if (gtid < BB * KK) {
        g_icnt[1][gtid] = 0;
        g_isum[1][3 * gtid + 0] = 0ull;
        g_isum[1][3 * gtid + 1] = 0ull;
        g_isum[1][3 * gtid + 2] = 0ull;
    }

    // ---- bin ALL 4096 batch points by cell, once (persistent tp/tpi/startP) ----
    if (tid < 256) sp->u.a.cntC[tid] = 0;
    __syncthreads();
#pragma unroll
    for (int j = 0; j < 8; j++) {
        int i = j * 512 + tid;
        const float* qp = pos + ((size_t)b * SS + i) * 3;
        int cell = (cellc(qp[2]) * NC + cellc(qp[1])) * NC + cellc(qp[0]);
        atomicAdd(&sp->u.a.cntC[cell], 1);
    }
    __syncthreads();
    scan256(sp->u.a.cntC, sp->startP, sp->wsums, tid);
#pragma unroll
    for (int j = 0; j < 8; j++) {
        int i = j * 512 + tid;
        const float* qp = pos + ((size_t)b * SS + i) * 3;
        float q0 = qp[0], q1 = qp[1], q2 = qp[2];
        int cell = (cellc(q2) * NC + cellc(q1)) * NC + cellc(q0);
        int slot = atomicAdd(&sp->u.a.cntC[cell], 1);
        sp->tp[slot] = make_float4(q0, q1, q2, norm3_nofma(q0, q1, q2));
        sp->tpi[slot] = (u16)i;
    }
    __syncthreads();
    // cell-aligned block cuts: cut[g] = startP[min{c : startP[c] >= g*512}]
    if (tid < 9) {
        int target = tid * 512;
        int c = 0;
        while (c < NCELLS && sp->startP[c] < target) c++;
        sp->cut[tid] = sp->startP[c];
    }
    grid_sync();   // covers init-zero + cuts

    // ================= K-MEANS: 5 iterations, one grid barrier each =========
    for (int it = 0; it < NITS; it++) {
        const int Rb = it % 3;
        const int Wb = (it + 1) % 3;
        const int Zb = (it + 2) % 3;

        // centroid k = tid
        float c0, c1, c2;
        if (it == 0) {
            const float* cp = pos + ((size_t)b * SS + tid) * 3;
            c0 = cp[0]; c1 = cp[1]; c2 = cp[2];
        } else {
            load_centroid(Rb, b, tid, c0, c1, c2);
        }
        const float cn = norm3_nofma(c0, c1, c2);
        const int ccell = (cellc(c2) * NC + cellc(c1)) * NC + cellc(c0);

        if (tid < 256) sp->u.a.cntC[tid] = 0;
        if (tid < 64) {           // zero Z-buffer slice
            int slot = blk * 64 + tid;
            g_icnt[Zb][slot] = 0;
            g_isum[Zb][3 * slot + 0] = 0ull;
            g_isum[Zb][3 * slot + 1] = 0ull;
            g_isum[Zb][3 * slot + 2] = 0ull;
        }
        __syncthreads();
        atomicAdd(&sp->u.a.cntC[ccell], 1);
        __syncthreads();
        scan256(sp->u.a.cntC, sp->u.a.startC, sp->wsums, tid);
        {
            int slot = atomicAdd(&sp->u.a.cntC[ccell], 1);
            sp->u.a.sc[slot] = make_float4(c0, c1, c2, cn);
            sp->u.a.sk[slot] = (u16)tid;
        }
        __syncthreads();

        // ---- assign over this block's cell-aligned slice of sorted points ----
        for (int idx = sp->cut[grp] + tid; idx < sp->cut[grp + 1]; idx += THREADS) {
            float4 pt = sp->tp[idx];
            const float p0 = pt.x, p1 = pt.y, p2 = pt.z, pn = pt.w;
            const int pix = cellc(p0), piy = cellc(p1), piz = cellc(p2);
            const int xlo = pix > 0 ? pix - 1 : 0, xhi = pix < 5 ? pix + 1 : 5;
            const int ylo = piy > 0 ? piy - 1 : 0, yhi = piy < 5 ? piy + 1 : 5;
            const int zlo = piz > 0 ? piz - 1 : 0, zhi = piz < 5 ? piz + 1 : 5;

            u64 bkey = 0xFFFFFFFFFFFFFFFFull;
            for (int z = zlo; z <= zhi; z++) {
                for (int y = ylo; y <= yhi; y++) {
                    int row = (z * NC + y) * NC;
                    int t0 = sp->u.a.startC[row + xlo];
                    int t1 = sp->u.a.startC[row + xhi + 1];
                    for (int t = t0; t < t1; t++) {
                        float4 c = sp->u.a.sc[t];
                        float dot = dot3_fma(p0, p1, p2, c.x, c.y, c.z);
                        float v = sqdist_combine(pn, dot, c.w);
                        u64 key = ((u64)float_ord(v) << 32) | sp->u.a.sk[t];
                        bkey = umin64(bkey, key);
                    }
                }
            }
            {
                float bestv = ord_inv((unsigned)(bkey >> 32));
                bool need = !(bestv < H2MARG);          // also catches empty (NaN)
                unsigned m = __activemask();
                if (__any_sync(m, need)) {              // rare
                    for (int t = 0; t < KK; t++) {
                        float4 c = sp->u.a.sc[t];
                        float dot = dot3_fma(p0, p1, p2, c.x, c.y, c.z);
                        float v = sqdist_combine(pn, dot, c.w);
                        u64 key = ((u64)float_ord(v) << 32) | sp->u.a.sk[t];
                        if (need) bkey = umin64(bkey, key);
                    }
                }
            }
            const int bi = (int)(bkey & 0xFFFFull);
            u64* sm = &g_isum[Wb][((size_t)b * KK + bi) * 3];
            atomicAdd(sm + 0, (u64)__double2ll_rn((double)p0 * FIXSCALE));
            atomicAdd(sm + 1, (u64)__double2ll_rn((double)p1 * FIXSCALE));
            atomicAdd(sm + 2, (u64)__double2ll_rn((double)p2 * FIXSCALE));
            atomicAdd(&g_icnt[Wb][b * KK + bi], 1);
        }
        grid_sync();
    }

    // ================= TOPK (in-block; reuses persistent sorted points) ======
    const int FB = NITS % 3;   // = 2
    if (tid == 0) sp->u.t.fbn = 0;

    {
        const int u = tid >> 3;           // local centroid 0..63
        const int j = tid & 7;            // lane within group
        const int k = grp * 64 + u;
        float c0, c1, c2;
        load_centroid(FB, b, k, c0, c1, c2);
        const float cn = norm3_nofma(c0, c1, c2);
        const int cx = cellc(c0), cy = cellc(c1), cz = cellc(c2);
        const int xlo = cx > 0 ? cx - 1 : 0, xhi = cx < 5 ? cx + 1 : 5;
        const int ylo = cy > 0 ? cy - 1 : 0, yhi = cy < 5 ? cy + 1 : 5;
        const int zlo = cz > 0 ? cz - 1 : 0, zhi = cz < 5 ? cz + 1 : 5;

        u64 l[PP];
#pragma unroll
        for (int q = 0; q < PP; q++) l[q] = 0xFF800000FFFFFFFFull;  // ord(+inf)|idx_max
        float thresh = __int_as_float(0x7f800000);

        for (int z = zlo; z <= zhi; z++) {
            for (int y = ylo; y <= yhi; y++) {
                int row = (z * NC + y) * NC;
                int t0 = sp->startP[row + xlo];
                int t1 = sp->startP[row + xhi + 1];
                for (int t = t0 + j; t < t1; t += 8) {
                    float4 p = sp->tp[t];
                    float dot = dot3_fma(c0, c1, c2, p.x, p.y, p.z);
                    float v = sqdist_combine(cn, dot, p.w);
                    top8_insert(l, thresh, v, (unsigned)sp->tpi[t]);
                }
            }
        }
#pragma unroll
        for (int q = 0; q < PP; q++) sp->u.t.part[u][j][q] = l[q];
    }
    __syncthreads();

    // ---- merge 8 partials per centroid; flag fallbacks ----
    if (tid < 64) {
        u64 a[PP];
#pragma unroll
        for (int q = 0; q < PP; q++) a[q] = sp->u.t.part[tid][0][q];
#pragma unroll
        for (int c = 1; c < 8; c++) merge8(a, sp->u.t.part[tid][c]);
#pragma unroll
        for (int q = 0; q < PP; q++) sp->u.t.sidx[tid][q] = (int)(a[q] & 0xFFFFu);
        float d7 = ord_inv((unsigned)(a[7] >> 32));
        if (!(d7 < H2MARG)) {
            int i = atomicAdd(&sp->u.t.fbn, 1);
            sp->u.t.fblist[i] = tid;
        }
    }
    __syncthreads();

    // ---- cooperative fallback: one warp per flagged centroid, exact full scan ----
    {
        const int warp = tid >> 5, lane = tid & 31;
        const int nfb = sp->u.t.fbn;
        for (int i = warp; i < nfb; i += 16) {
            int u = sp->u.t.fblist[i];
            int k = grp * 64 + u;
            float c0, c1, c2;
            load_centroid(FB, b, k, c0, c1, c2);
            float cn = norm3_nofma(c0, c1, c2);
            u64 l[PP];
#pragma unroll
            for (int q = 0; q < PP; q++) l[q] = 0xFF800000FFFFFFFFull;
            float thresh = __int_as_float(0x7f800000);
            for (int t = lane; t < SS; t += 32) {
                float4 p = sp->tp[t];
                float dot = dot3_fma(c0, c1, c2, p.x, p.y, p.z);
                float v = sqdist_combine(cn, dot, p.w);
                top8_insert(l, thresh, v, (unsigned)sp->tpi[t]);
            }
            u64* reg = &sp->u.t.part[4 * warp][0][0];   // warp's own scratch (256 slots)
#pragma unroll
            for (int q = 0; q < PP; q++) reg[lane * 8 + q] = l[q];
            __syncwarp();
            if (lane == 0) {
                u64 a[PP];
#pragma unroll
                for (int q = 0; q < PP; q++) a[q] = reg[q];
                for (int c = 1; c < 32; c++) merge8(a, &reg[c * 8]);
#pragma unroll
                for (int q = 0; q < PP; q++) sp->u.t.sidx[u][q] = (int)(a[q] & 0xFFFFu);
            }
            __syncwarp();
        }
    }
    __syncthreads();

    // ---- gather-mean in float4: 8 teams of 64 threads, MLP=8 ----
    {
        const float4* xb4 = reinterpret_cast<const float4*>(x) + (size_t)b * SS * (FF / 4);
        float4* ob4 = reinterpret_cast<float4*>(out) + ((size_t)b * KK + grp * 64) * (FF / 4);
        const int g8 = tid >> 6;       // team 0..7
        const int lane64 = tid & 63;   // float4 column
        for (int uu = 0; uu < 8; uu++) {
            int u = g8 * 8 + uu;
            const int* si = sp->u.t.sidx[u];
            float acc0 = 0.f, acc1 = 0.f, acc2 = 0.f, acc3 = 0.f;
#pragma unroll
            for (int p = 0; p < 8; p++) {
                float4 v = __ldg(&xb4[(size_t)si[p] * (FF / 4) + lane64]);
                acc0 += v.x; acc1 += v.y; acc2 += v.z; acc3 += v.w;
            }
            ob4[(size_t)u * (FF / 4) + lane64] =
                make_float4(acc0 * 0.125f, acc1 * 0.125f, acc2 * 0.125f, acc3 * 0.125f);
        }
    }
}

// ---------------- launch ----------------
extern "C" void kernel_launch(void* const* d_in, const int* in_sizes, int n_in,
                              void* d_out, int out_size) {
    const float* x   = (const float*)d_in[0];   // (B,S,F) f32
    const float* pos = (const float*)d_in[1];   // (B,S,D) f32
    float* out = (float*)d_out;                 // (B,K,F) f32
    (void)in_sizes; (void)n_in; (void)out_size;

    cudaFuncSetAttribute(mega, cudaFuncAttributeMaxDynamicSharedMemorySize,
                         (int)sizeof(SP));
    mega<<<GRID, THREADS, sizeof(SP)>>>(x, pos, out);
}

// round 9
// speedup vs baseline: 1.9656x; 1.0558x over previous
#include <cuda_runtime.h>
#include <cstdint>

#define BB 16
#define SS 4096
#define FF 256
#define KK 512
#define PP 8
#define NITS 5
#define GRID 128
#define THREADS 512
#define BLKS_PER_BATCH 8
#define FIXSCALE 1099511627776.0   // 2^40
#define NC 6
#define NCELLS 216
#define H2MARG 0.0276778f          // (1/6)^2 - 1e-4 safety margin

typedef unsigned long long u64;
typedef unsigned short u16;

// ---------------- device scratch ----------------
static __device__ u64 g_isum[3][BB * KK * 3];   // triple-buffered fixed-point sums
static __device__ int g_icnt[3][BB * KK];       // triple-buffered counts

struct Bar { unsigned cnt; unsigned phase; unsigned pad[30]; };  // 128B, own line
static __device__ Bar g_bars[BB];

// ---------------- dynamic smem layout ----------------
struct SP {
    float4 tp[SS];        // 64KB: batch points, cell-sorted (persistent)
    u16 tpi[SS];          // 8KB: original s of sorted point (persistent)
    int startP[257];      // point-cell starts (persistent)
    int wsums[8];         // scan scratch
    int cut[9];           // cell-aligned block slice cuts
    union {
        struct {          // assign phase (~11KB)
            float4 sc[KK];      // cell-sorted centroids
            u16 sk[KK];         // original k
            int cntC[256];      // counters / cursors
            int startC[257];
        } a;
        struct {          // topk phase (~35KB)
            u64 part[64][8][PP];
            int sidx[64][PP];
            int fblist[64];
            int fbn;
        } t;
    } u;
};

// ---------------- FP helpers (reference-exact semantics) --------
__device__ __forceinline__ unsigned float_ord(float f) {
    unsigned u = __float_as_uint(f);
    return (u & 0x80000000u) ? ~u : (u | 0x80000000u);
}
__device__ __forceinline__ float ord_inv(unsigned u) {
    return __uint_as_float((u & 0x80000000u) ? (u & 0x7FFFFFFFu) : ~u);
}
__device__ __forceinline__ u64 umin64(u64 a, u64 b) { return a < b ? a : b; }
// mirrors jnp.sum(a*a,-1): elementwise mul then sequential reduce (no FMA contraction)
__device__ __forceinline__ float norm3_nofma(float a0, float a1, float a2) {
    return __fadd_rn(__fadd_rn(__fmul_rn(a0, a0), __fmul_rn(a1, a1)), __fmul_rn(a2, a2));
}
// ascending-d fma chain
__device__ __forceinline__ float dot3_fma(float a0, float a1, float a2,
                                          float b0, float b1, float b2) {
    return __fmaf_rn(a2, b2, __fmaf_rn(a1, b1, __fmul_rn(a0, b0)));
}
// (aa - 2*dot) + bb, reference grouping
__device__ __forceinline__ float sqdist_combine(float aa, float dot, float bb) {
    return __fadd_rn(__fmaf_rn(-2.0f, dot, aa), bb);
}
__device__ __forceinline__ int cellc(float x) {
    int i = (int)floorf(x * 6.0f);
    return i < 0 ? 0 : (i > 5 ? 5 : i);
}

__device__ __forceinline__ void sort8_bitonic(u64 v[8]) {
#define CSWP(i, j) { u64 lo = umin64(v[i], v[j]); \
                     u64 hi = (v[i] < v[j]) ? v[j] : v[i]; \
                     v[i] = lo; v[j] = hi; }
    CSWP(0, 4) CSWP(1, 5) CSWP(2, 6) CSWP(3, 7)
    CSWP(0, 2) CSWP(1, 3) CSWP(4, 6) CSWP(5, 7)
    CSWP(0, 1) CSWP(2, 3) CSWP(4, 5) CSWP(6, 7)
#undef CSWP
}
__device__ __forceinline__ void merge8(u64 a[8], const u64 b[8]) {
    u64 m[8];
#pragma unroll
    for (int i = 0; i < 8; i++) m[i] = umin64(a[i], b[7 - i]);
    sort8_bitonic(m);
#pragma unroll
    for (int i = 0; i < 8; i++) a[i] = m[i];
}

// sorted-insert; <= lets equal-dist smaller-idx keys reach the key compare
__device__ __forceinline__ void top8_insert(u64 l[PP], float& thresh, float v, unsigned idx) {
    if (v <= thresh) {
        float vc = (v == 0.0f) ? 0.0f : v;   // canonicalize -0.0
        u64 key = ((u64)float_ord(vc) << 32) | idx;
        if (key < l[7]) {
            l[7] = key;
#pragma unroll
            for (int j = 7; j > 0; --j)
                if (l[j] < l[j - 1]) { u64 tt = l[j]; l[j] = l[j - 1]; l[j - 1] = tt; }
            thresh = ord_inv((unsigned)(l[7] >> 32));
        }
    }
}

// shfl-based 256-entry scan: counts in cnt[] -> starts in startArr[0..256],
// exclusive cursors written back into cnt[]. 3 block barriers.
__device__ __forceinline__ void scan256(int* cnt, int* startArr, int* wsums, int tid) {
    int w = tid >> 5, lane = tid & 31;
    int orig = 0, v = 0;
    if (tid < 256) {
        orig = cnt[tid]; v = orig;
#pragma unroll
        for (int off = 1; off < 32; off <<= 1) {
            int n = __shfl_up_sync(0xFFFFFFFFu, v, off);
            if (lane >= off) v += n;
        }
        if (lane == 31) wsums[w] = v;
    }
    __syncthreads();
    if (tid < 8) {
        int s = wsums[tid];
#pragma unroll
        for (int off = 1; off < 8; off <<= 1) {
            int n = __shfl_up_sync(0xFFu, s, off);
            if (tid >= off) s += n;
        }
        wsums[tid] = s;
    }
    __syncthreads();
    if (tid < 256) {
        int incl = v + (w > 0 ? wsums[w - 1] : 0);
        startArr[tid + 1] = incl;
        cnt[tid] = incl - orig;       // exclusive prefix = scatter cursor
    }
    if (tid == 0) startArr[0] = 0;
    __syncthreads();
}

// ---------------- per-batch barrier (8 blocks, all co-resident) ----
__device__ __forceinline__ void batch_sync(int b) {
    __syncthreads();
    if (threadIdx.x == 0) {
        __threadfence();
        unsigned gen = atomicAdd(&g_bars[b].phase, 0u);
        if (atomicAdd(&g_bars[b].cnt, 1u) == BLKS_PER_BATCH - 1) {
            g_bars[b].cnt = 0;
            __threadfence();
            atomicAdd(&g_bars[b].phase, 1u);  // release
        } else {
            while (atomicAdd(&g_bars[b].phase, 0u) == gen) __nanosleep(32);
        }
        __threadfence();
    }
    __syncthreads();
}

__device__ __forceinline__ void load_centroid(int fb, int b, int k,
                                              float& c0, float& c1, float& c2) {
    int slot = b * KK + k;
    float cnt = (float)g_icnt[fb][slot];
    cnt = cnt > 1.0f ? cnt : 1.0f;
    c0 = __fdiv_rn((float)((double)(long long)g_isum[fb][3 * slot + 0] * (1.0 / FIXSCALE)), cnt);
    c1 = __fdiv_rn((float)((double)(long long)g_isum[fb][3 * slot + 1] * (1.0 / FIXSCALE)), cnt);
    c2 = __fdiv_rn((float)((double)(long long)g_isum[fb][3 * slot + 2] * (1.0 / FIXSCALE)), cnt);
}

// ---------------- megakernel ----------------
__global__ void __launch_bounds__(THREADS, 1)
mega(const float* __restrict__ x, const float* __restrict__ pos, float* __restrict__ out) {
    extern __shared__ char smem_raw[];
    SP* sp = reinterpret_cast<SP*>(smem_raw);

    const int tid = threadIdx.x;
    const int blk = blockIdx.x;
    const int b = blk >> 3;               // batch (8 blocks per batch)
    const int grp = blk & 7;              // group within batch

    // ---- init: zero buffer 1, batch-local (this block's 64 slots) ----
    if (tid < 64) {
        int slot = blk * 64 + tid;        // within batch b's [b*512, b*512+512) range
        g_icnt[1][slot] = 0;
        g_isum[1][3 * slot + 0] = 0ull;
        g_isum[1][3 * slot + 1] = 0ull;
        g_isum[1][3 * slot + 2] = 0ull;
    }

    // ---- bin ALL 4096 batch points by cell, once (persistent tp/tpi/startP) ----
    if (tid < 256) sp->u.a.cntC[tid] = 0;
    __syncthreads();
#pragma unroll
    for (int j = 0; j < 8; j++) {
        int i = j * 512 + tid;
        const float* qp = pos + ((size_t)b * SS + i) * 3;
        int cell = (cellc(qp[2]) * NC + cellc(qp[1])) * NC + cellc(qp[0]);
        atomicAdd(&sp->u.a.cntC[cell], 1);
    }
    __syncthreads();
    scan256(sp->u.a.cntC, sp->startP, sp->wsums, tid);
#pragma unroll
    for (int j = 0; j < 8; j++) {
        int i = j * 512 + tid;
        const float* qp = pos + ((size_t)b * SS + i) * 3;
        float q0 = qp[0], q1 = qp[1], q2 = qp[2];
        int cell = (cellc(q2) * NC + cellc(q1)) * NC + cellc(q0);
        int slot = atomicAdd(&sp->u.a.cntC[cell], 1);
        sp->tp[slot] = make_float4(q0, q1, q2, norm3_nofma(q0, q1, q2));
        sp->tpi[slot] = (u16)i;
    }
    __syncthreads();
    // cell-aligned block cuts: cut[g] = startP[min{c : startP[c] >= g*512}]
    if (tid < 9) {
        int target = tid * 512;
        int c = 0;
        while (c < NCELLS && sp->startP[c] < target) c++;
        sp->cut[tid] = sp->startP[c];
    }
    batch_sync(b);   // covers init-zero + cuts (all batch-local)

    // ================= K-MEANS: 5 iterations, one batch barrier each =========
    for (int it = 0; it < NITS; it++) {
        const int Rb = it % 3;
        const int Wb = (it + 1) % 3;
        const int Zb = (it + 2) % 3;

        // centroid k = tid
        float c0, c1, c2;
        if (it == 0) {
            const float* cp = pos + ((size_t)b * SS + tid) * 3;
            c0 = cp[0]; c1 = cp[1]; c2 = cp[2];
        } else {
            load_centroid(Rb, b, tid, c0, c1, c2);
        }
        const float cn = norm3_nofma(c0, c1, c2);
        const int ccell = (cellc(c2) * NC + cellc(c1)) * NC + cellc(c0);

        if (tid < 256) sp->u.a.cntC[tid] = 0;
        if (tid < 64) {           // zero Z-buffer slice (batch-local)
            int slot = blk * 64 + tid;
            g_icnt[Zb][slot] = 0;
            g_isum[Zb][3 * slot + 0] = 0ull;
            g_isum[Zb][3 * slot + 1] = 0ull;
            g_isum[Zb][3 * slot + 2] = 0ull;
        }
        __syncthreads();
        atomicAdd(&sp->u.a.cntC[ccell], 1);
        __syncthreads();
        scan256(sp->u.a.cntC, sp->u.a.startC, sp->wsums, tid);
        {
            int slot = atomicAdd(&sp->u.a.cntC[ccell], 1);
            sp->u.a.sc[slot] = make_float4(c0, c1, c2, cn);
            sp->u.a.sk[slot] = (u16)tid;
        }
        __syncthreads();

        // ---- assign over this block's cell-aligned slice of sorted points ----
        for (int idx = sp->cut[grp] + tid; idx < sp->cut[grp + 1]; idx += THREADS) {
            float4 pt = sp->tp[idx];
            const float p0 = pt.x, p1 = pt.y, p2 = pt.z, pn = pt.w;
            const int pix = cellc(p0), piy = cellc(p1), piz = cellc(p2);
            const int xlo = pix > 0 ? pix - 1 : 0, xhi = pix < 5 ? pix + 1 : 5;
            const int ylo = piy > 0 ? piy - 1 : 0, yhi = piy < 5 ? piy + 1 : 5;
            const int zlo = piz > 0 ? piz - 1 : 0, zhi = piz < 5 ? piz + 1 : 5;

            u64 bkey = 0xFFFFFFFFFFFFFFFFull;
            for (int z = zlo; z <= zhi; z++) {
                for (int y = ylo; y <= yhi; y++) {
                    int row = (z * NC + y) * NC;
                    int t0 = sp->u.a.startC[row + xlo];
                    int t1 = sp->u.a.startC[row + xhi + 1];
                    int t = t0;
                    // unroll-by-2: two independent distance chains
                    for (; t + 1 < t1; t += 2) {
                        float4 ca = sp->u.a.sc[t];
                        float4 cb = sp->u.a.sc[t + 1];
                        float da = dot3_fma(p0, p1, p2, ca.x, ca.y, ca.z);
                        float db = dot3_fma(p0, p1, p2, cb.x, cb.y, cb.z);
                        float va = sqdist_combine(pn, da, ca.w);
                        float vb = sqdist_combine(pn, db, cb.w);
                        u64 ka = ((u64)float_ord(va) << 32) | sp->u.a.sk[t];
                        u64 kb = ((u64)float_ord(vb) << 32) | sp->u.a.sk[t + 1];
                        bkey = umin64(bkey, umin64(ka, kb));
                    }
                    if (t < t1) {
                        float4 c = sp->u.a.sc[t];
                        float dot = dot3_fma(p0, p1, p2, c.x, c.y, c.z);
                        float v = sqdist_combine(pn, dot, c.w);
                        bkey = umin64(bkey, ((u64)float_ord(v) << 32) | sp->u.a.sk[t]);
                    }
                }
            }
            {
                float bestv = ord_inv((unsigned)(bkey >> 32));
                bool need = !(bestv < H2MARG);          // also catches empty (NaN)
                unsigned m = __activemask();
                if (__any_sync(m, need)) {              // rare
                    for (int t = 0; t < KK; t++) {
                        float4 c = sp->u.a.sc[t];
                        float dot = dot3_fma(p0, p1, p2, c.x, c.y, c.z);
                        float v = sqdist_combine(pn, dot, c.w);
                        u64 key = ((u64)float_ord(v) << 32) | sp->u.a.sk[t];
                        if (need) bkey = umin64(bkey, key);
                    }
                }
            }
            const int bi = (int)(bkey & 0xFFFFull);
            u64* sm = &g_isum[Wb][((size_t)b * KK + bi) * 3];
            atomicAdd(sm + 0, (u64)__double2ll_rn((double)p0 * FIXSCALE));
            atomicAdd(sm + 1, (u64)__double2ll_rn((double)p1 * FIXSCALE));
            atomicAdd(sm + 2, (u64)__double2ll_rn((double)p2 * FIXSCALE));
            atomicAdd(&g_icnt[Wb][b * KK + bi], 1);
        }
        batch_sync(b);
    }

    // ================= TOPK (in-block; reuses persistent sorted points) ======
    const int FB = NITS % 3;   // = 2
    if (tid == 0) sp->u.t.fbn = 0;

    {
        const int u = tid >> 3;           // local centroid 0..63
        const int j = tid & 7;            // lane within group
        const int k = grp * 64 + u;
        float c0, c1, c2;
        load_centroid(FB, b, k, c0, c1, c2);
        const float cn = norm3_nofma(c0, c1, c2);
        const int cx = cellc(c0), cy = cellc(c1), cz = cellc(c2);
        const int xlo = cx > 0 ? cx - 1 : 0, xhi = cx < 5 ? cx + 1 : 5;
        const int ylo = cy > 0 ? cy - 1 : 0, yhi = cy < 5 ? cy + 1 : 5;
        const int zlo = cz > 0 ? cz - 1 : 0, zhi = cz < 5 ? cz + 1 : 5;

        u64 l[PP];
#pragma unroll
        for (int q = 0; q < PP; q++) l[q] = 0xFF800000FFFFFFFFull;  // ord(+inf)|idx_max
        float thresh = __int_as_float(0x7f800000);

        for (int z = zlo; z <= zhi; z++) {
            for (int y = ylo; y <= yhi; y++) {
                int row = (z * NC + y) * NC;
                int t0 = sp->startP[row + xlo];
                int t1 = sp->startP[row + xhi + 1];
                int t = t0 + j;
                // unroll-by-2 (insert order preserved: t then t+8)
                for (; t + 8 < t1; t += 16) {
                    float4 pa = sp->tp[t];
                    float4 pb = sp->tp[t + 8];
                    float da = dot3_fma(c0, c1, c2, pa.x, pa.y, pa.z);
                    float db = dot3_fma(c0, c1, c2, pb.x, pb.y, pb.z);
                    float va = sqdist_combine(cn, da, pa.w);
                    float vb = sqdist_combine(cn, db, pb.w);
                    top8_insert(l, thresh, va, (unsigned)sp->tpi[t]);
                    top8_insert(l, thresh, vb, (unsigned)sp->tpi[t + 8]);
                }
                if (t < t1) {
                    float4 p = sp->tp[t];
                    float dot = dot3_fma(c0, c1, c2, p.x, p.y, p.z);
                    float v = sqdist_combine(cn, dot, p.w);
                    top8_insert(l, thresh, v, (unsigned)sp->tpi[t]);
                }
            }
        }
#pragma unroll
        for (int q = 0; q < PP; q++) sp->u.t.part[u][j][q] = l[q];
    }
    __syncthreads();

    // ---- merge 8 partials per centroid; flag fallbacks ----
    if (tid < 64) {
        u64 a[PP];
#pragma unroll
        for (int q = 0; q < PP; q++) a[q] = sp->u.t.part[tid][0][q];
#pragma unroll
        for (int c = 1; c < 8; c++) merge8(a, sp->u.t.part[tid][c]);
#pragma unroll
        for (int q = 0; q < PP; q++) sp->u.t.sidx[tid][q] = (int)(a[q] & 0xFFFFu);
        float d7 = ord_inv((unsigned)(a[7] >> 32));
        if (!(d7 < H2MARG)) {
            int i = atomicAdd(&sp->u.t.fbn, 1);
            sp->u.t.fblist[i] = tid;
        }
    }
    __syncthreads();

    // ---- cooperative fallback: one warp per flagged centroid, exact full scan ----
    {
        const int warp = tid >> 5, lane = tid & 31;
        const int nfb = sp->u.t.fbn;
        for (int i = warp; i < nfb; i += 16) {
            int u = sp->u.t.fblist[i];
            int k = grp * 64 + u;
            float c0, c1, c2;
            load_centroid(FB, b, k, c0, c1, c2);
            float cn = norm3_nofma(c0, c1, c2);
            u64 l[PP];
#pragma unroll
            for (int q = 0; q < PP; q++) l[q] = 0xFF800000FFFFFFFFull;
            float thresh = __int_as_float(0x7f800000);
            for (int t = lane; t < SS; t += 32) {
                float4 p = sp->tp[t];
                float dot = dot3_fma(c0, c1, c2, p.x, p.y, p.z);
                float v = sqdist_combine(cn, dot, p.w);
                top8_insert(l, thresh, v, (unsigned)sp->tpi[t]);
            }
            u64* reg = &sp->u.t.part[4 * warp][0][0];   // warp's own scratch (256 slots)
#pragma unroll
            for (int q = 0; q < PP; q++) reg[lane * 8 + q] = l[q];
            __syncwarp();
            if (lane == 0) {
                u64 a[PP];
#pragma unroll
                for (int q = 0; q < PP; q++) a[q] = reg[q];
                for (int c = 1; c < 32; c++) merge8(a, &reg[c * 8]);
#pragma unroll
                for (int q = 0; q < PP; q++) sp->u.t.sidx[u][q] = (int)(a[q] & 0xFFFFu);
            }
            __syncwarp();
        }
    }
    __syncthreads();

    // ---- gather-mean in float4: 8 teams of 64 threads, MLP=8 ----
    {
        const float4* xb4 = reinterpret_cast<const float4*>(x) + (size_t)b * SS * (FF / 4);
        float4* ob4 = reinterpret_cast<float4*>(out) + ((size_t)b * KK + grp * 64) * (FF / 4);
        const int g8 = tid >> 6;       // team 0..7
        const int lane64 = tid & 63;   // float4 column
        for (int uu = 0; uu < 8; uu++) {
            int u = g8 * 8 + uu;
            const int* si = sp->u.t.sidx[u];
            float acc0 = 0.f, acc1 = 0.f, acc2 = 0.f, acc3 = 0.f;
#pragma unroll
            for (int p = 0; p < 8; p++) {
                float4 v = __ldg(&xb4[(size_t)si[p] * (FF / 4) + lane64]);
                acc0 += v.x; acc1 += v.y; acc2 += v.z; acc3 += v.w;
            }
            ob4[(size_t)u * (FF / 4) + lane64] =
                make_float4(acc0 * 0.125f, acc1 * 0.125f, acc2 * 0.125f, acc3 * 0.125f);
        }
    }
}

// ---------------- launch ----------------
extern "C" void kernel_launch(void* const* d_in, const int* in_sizes, int n_in,
                              void* d_out, int out_size) {
    const float* x   = (const float*)d_in[0];   // (B,S,F) f32
    const float* pos = (const float*)d_in[1];   // (B,S,D) f32
    float* out = (float*)d_out;                 // (B,K,F) f32
    (void)in_sizes; (void)n_in; (void)out_size;

    cudaFuncSetAttribute(mega, cudaFuncAttributeMaxDynamicSharedMemorySize,
                         (int)sizeof(SP));
    mega<<<GRID, THREADS, sizeof(SP)>>>(x, pos, out);
}